// round 5
// baseline (speedup 1.0000x reference)
#include <cuda_runtime.h>

// Problem constants
#define Bc 16
#define Dc 64
#define Tc 8192
#define Kc 512
#define DT (Dc * Tc)        // 524288
#define BT (Bc * Tc)        // 131072
#define THREADS 384
#define GRID 148
#define TPC (2 * THREADS)   // 768 tokens per CTA round (2 per thread)

// smem: plain codebook [512][64] fp32 + cn[512]
#define SMEM_BYTES ((Kc * Dc + Kc) * 4)   // 133120 B

typedef unsigned long long ull;

// one dup'd-c FMA2 step: serial-in-d chain for both tokens (lanewise fp32 exact)
#define STEP(acc, fsrc, xreg) do {                                          \
    ull c_;                                                                 \
    asm("mov.b64 %0, {%1, %1};" : "=l"(c_) : "f"(fsrc));                    \
    asm("fma.rn.f32x2 %0, %1, %2, %0;" : "+l"(acc) : "l"(c_), "l"(xreg));   \
} while (0)

__global__ __launch_bounds__(THREADS, 1)
void vq_kernel(const float* __restrict__ x,
               const float* __restrict__ cb,
               float* __restrict__ out,
               int write_second)
{
    extern __shared__ float smem[];
    float* scb = smem;             // [512][64] row-major
    float* scn = smem + Kc * Dc;   // [512]

    const int tid = threadIdx.x;

    // ---- cooperative codebook load ----
    {
        const float4* s4 = (const float4*)cb;
        float4* d4 = (float4*)scb;
        for (int i = tid; i < (Kc * Dc) / 4; i += THREADS)
            d4[i] = s4[i];
    }
    __syncthreads();
    // ---- cn[k]: serial round(mul)+add ascending d ----
    for (int k = tid; k < Kc; k += THREADS) {
        float s = 0.f;
        #pragma unroll
        for (int d = 0; d < Dc; d++) {
            float c = scb[k * Dc + d];
            s = __fadd_rn(s, __fmul_rn(c, c));
        }
        scn[k] = s;
    }
    __syncthreads();

    unsigned scb_addr;
    asm("{ .reg .u64 tt; cvta.to.shared.u64 tt, %1; cvt.u32.u64 %0, tt; }"
        : "=r"(scb_addr) : "l"(scb));

    ull m2;   // {-2.0f, -2.0f}
    {
        float mm = -2.0f;
        asm("mov.b64 %0, {%1, %1};" : "=l"(m2) : "f"(mm));
    }

    // ---- grid-stride: each thread owns token0 = base+tid, token1 = token0+384 ----
    for (int base = blockIdx.x * TPC; base < BT; base += GRID * TPC) {
        const int token0 = base + tid;
        const int token1 = token0 + THREADS;
        if (token0 >= BT) break;                 // tail CTA, idle upper threads
        const int ok1 = (token1 < BT);

        const int b0 = token0 >> 13, t0 = token0 & (Tc - 1);
        const int b1 = token1 >> 13, t1 = token1 & (Tc - 1);
        const float* xp0 = x + (size_t)b0 * DT + t0;
        const float* xp1 = x + (size_t)b1 * DT + t1;

        // x packed {x_t0[d], x_t1[d]}; xn serial per token (exact fp32)
        ull xv[Dc];
        float xn0 = 0.f, xn1 = 0.f;
        #pragma unroll
        for (int d = 0; d < Dc; d++) {
            const float v0 = xp0[(size_t)d * Tc];
            const float v1 = ok1 ? xp1[(size_t)d * Tc] : 0.f;
            xn0 = __fadd_rn(xn0, __fmul_rn(v0, v0));
            xn1 = __fadd_rn(xn1, __fmul_rn(v1, v1));
            asm("mov.b64 %0, {%1, %2};" : "=l"(xv[d]) : "f"(v0), "f"(v1));
        }
        ull xnp;
        asm("mov.b64 %0, {%1, %2};" : "=l"(xnp) : "f"(xn0), "f"(xn1));

        float best0 = 3.4e38f, best1 = 3.4e38f;
        int bi0 = 0, bi1 = 0;

        // ---- 256 blocks of 2 codewords; each lane = one token, serial d chain ----
        #pragma unroll 1
        for (int kb = 0; kb < Kc; kb += 2) {
            const unsigned r0 = scb_addr + (unsigned)kb * (Dc * 4);
            ull a0 = 0ull, a1 = 0ull;

            #pragma unroll
            for (int g = 0; g < 16; g++) {
                float f00, f01, f02, f03, f10, f11, f12, f13;
                asm("ld.shared.v4.f32 {%0,%1,%2,%3}, [%4];"
                    : "=f"(f00), "=f"(f01), "=f"(f02), "=f"(f03)
                    : "r"(r0 + g * 16));
                asm("ld.shared.v4.f32 {%0,%1,%2,%3}, [%4];"
                    : "=f"(f10), "=f"(f11), "=f"(f12), "=f"(f13)
                    : "r"(r0 + 256 + g * 16));
                STEP(a0, f00, xv[4 * g + 0]);
                STEP(a1, f10, xv[4 * g + 0]);
                STEP(a0, f01, xv[4 * g + 1]);
                STEP(a1, f11, xv[4 * g + 1]);
                STEP(a0, f02, xv[4 * g + 2]);
                STEP(a1, f12, xv[4 * g + 2]);
                STEP(a0, f03, xv[4 * g + 3]);
                STEP(a1, f13, xv[4 * g + 3]);
            }

            // s1 = round(-2*dot + xn); score = round(s1 + cn); ascending k, strict <
            ull s0p, s1p;
            asm("fma.rn.f32x2 %0, %1, %2, %3;" : "=l"(s0p) : "l"(a0), "l"(m2), "l"(xnp));
            asm("fma.rn.f32x2 %0, %1, %2, %3;" : "=l"(s1p) : "l"(a1), "l"(m2), "l"(xnp));
            float p00, p01, p10, p11;
            asm("mov.b64 {%0, %1}, %2;" : "=f"(p00), "=f"(p01) : "l"(s0p));
            asm("mov.b64 {%0, %1}, %2;" : "=f"(p10), "=f"(p11) : "l"(s1p));
            const float cn0 = scn[kb], cn1 = scn[kb + 1];
            float sc;
            sc = __fadd_rn(p00, cn0); if (sc < best0) { best0 = sc; bi0 = kb; }
            sc = __fadd_rn(p10, cn1); if (sc < best0) { best0 = sc; bi0 = kb + 1; }
            sc = __fadd_rn(p01, cn0); if (sc < best1) { best1 = sc; bi1 = kb; }
            sc = __fadd_rn(p11, cn1); if (sc < best1) { best1 = sc; bi1 = kb + 1; }
        }

        // ---- gather + write both tokens, both outputs ----
        {
            float* o0 = out + (size_t)b0 * DT + t0;
            const float4* q0 = (const float4*)(scb + bi0 * Dc);
            #pragma unroll
            for (int g = 0; g < 16; g++) {
                const float4 qa = q0[g];
                const size_t r = (size_t)(4 * g) * Tc;
                o0[r] = qa.x; o0[r + Tc] = qa.y; o0[r + 2 * Tc] = qa.z; o0[r + 3 * Tc] = qa.w;
                if (write_second) {
                    float* p0 = o0 + (size_t)Bc * DT;
                    p0[r] = qa.x; p0[r + Tc] = qa.y; p0[r + 2 * Tc] = qa.z; p0[r + 3 * Tc] = qa.w;
                }
            }
        }
        if (ok1) {
            float* o1 = out + (size_t)b1 * DT + t1;
            const float4* q1 = (const float4*)(scb + bi1 * Dc);
            #pragma unroll
            for (int g = 0; g < 16; g++) {
                const float4 qb = q1[g];
                const size_t r = (size_t)(4 * g) * Tc;
                o1[r] = qb.x; o1[r + Tc] = qb.y; o1[r + 2 * Tc] = qb.z; o1[r + 3 * Tc] = qb.w;
                if (write_second) {
                    float* p1 = o1 + (size_t)Bc * DT;
                    p1[r] = qb.x; p1[r + Tc] = qb.y; p1[r + 2 * Tc] = qb.z; p1[r + 3 * Tc] = qb.w;
                }
            }
        }
    }
}

extern "C" void kernel_launch(void* const* d_in, const int* in_sizes, int n_in,
                              void* d_out, int out_size)
{
    const float* x  = (const float*)d_in[0];   // [16, 64, 8192] fp32
    const float* cb = (const float*)d_in[1];   // [512, 64] fp32
    float* out = (float*)d_out;                // 2 x [16,64,8192]

    static int smem_set = 0;
    if (!smem_set) {
        cudaFuncSetAttribute(vq_kernel,
                             cudaFuncAttributeMaxDynamicSharedMemorySize,
                             SMEM_BYTES);
        smem_set = 1;
    }

    const int write_second = (out_size >= 2 * Bc * DT) ? 1 : 0;
    vq_kernel<<<GRID, THREADS, SMEM_BYTES>>>(x, cb, out, write_second);
}

// round 6
// speedup vs baseline: 1.4852x; 1.4852x over previous
#include <cuda_runtime.h>

// Problem constants
#define Bc 16
#define Dc 64
#define Tc 8192
#define Kc 512
#define DT (Dc * Tc)        // 524288
#define BT (Bc * Tc)        // 131072
#define THREADS 256
#define GRID 148
#define TPC (2 * THREADS)   // 512 tokens per CTA round (2 per thread)

// smem: plain codebook [512][64] fp32 + cn[512]
#define SMEM_BYTES ((Kc * Dc + Kc) * 4)   // 133120 B

typedef unsigned long long ull;

// one dup'd-c FMA2 step: serial-in-d chain for both tokens (lanewise fp32 exact)
#define STEP(acc, fsrc, xreg) do {                                          \
    ull c_;                                                                 \
    asm("mov.b64 %0, {%1, %1};" : "=l"(c_) : "f"(fsrc));                    \
    asm("fma.rn.f32x2 %0, %1, %2, %0;" : "+l"(acc) : "l"(c_), "l"(xreg));   \
} while (0)

__global__ __launch_bounds__(THREADS, 1)
void vq_kernel(const float* __restrict__ x,
               const float* __restrict__ cb,
               float* __restrict__ out,
               int write_second)
{
    extern __shared__ float smem[];
    float* scb = smem;             // [512][64] row-major
    float* scn = smem + Kc * Dc;   // [512]

    const int tid = threadIdx.x;

    // ---- cooperative codebook load ----
    {
        const float4* s4 = (const float4*)cb;
        float4* d4 = (float4*)scb;
        for (int i = tid; i < (Kc * Dc) / 4; i += THREADS)
            d4[i] = s4[i];
    }
    __syncthreads();
    // ---- cn[k]: serial round(mul)+add ascending d ----
    for (int k = tid; k < Kc; k += THREADS) {
        float s = 0.f;
        #pragma unroll
        for (int d = 0; d < Dc; d++) {
            float c = scb[k * Dc + d];
            s = __fadd_rn(s, __fmul_rn(c, c));
        }
        scn[k] = s;
    }
    __syncthreads();

    unsigned scb_addr;
    asm("{ .reg .u64 tt; cvta.to.shared.u64 tt, %1; cvt.u32.u64 %0, tt; }"
        : "=r"(scb_addr) : "l"(scb));

    ull m2;   // {-2.0f, -2.0f}
    {
        float mm = -2.0f;
        asm("mov.b64 %0, {%1, %1};" : "=l"(m2) : "f"(mm));
    }

    // ---- grid-stride: thread owns tokens base+tid and base+tid+256 (same b) ----
    for (int base = blockIdx.x * TPC; base < BT; base += GRID * TPC) {
        const int b = base >> 13;                  // base multiple of 512 -> same b
        const int t0 = (base & (Tc - 1)) + tid;
        const float* xrow = x + (size_t)b * DT;

        // x packed {x_t0[d], x_t1[d]}; xn serial per token (exact fp32)
        ull xv[Dc];
        float xn0 = 0.f, xn1 = 0.f;
        #pragma unroll
        for (int d = 0; d < Dc; d++) {
            const float v0 = xrow[(size_t)d * Tc + t0];
            const float v1 = xrow[(size_t)d * Tc + t0 + THREADS];
            xn0 = __fadd_rn(xn0, __fmul_rn(v0, v0));
            xn1 = __fadd_rn(xn1, __fmul_rn(v1, v1));
            asm("mov.b64 %0, {%1, %2};" : "=l"(xv[d]) : "f"(v0), "f"(v1));
        }
        ull xnp;
        asm("mov.b64 %0, {%1, %2};" : "=l"(xnp) : "f"(xn0), "f"(xn1));

        float best0 = 3.4e38f, best1 = 3.4e38f;
        int bi0 = 0, bi1 = 0;

        // ---- blocks of 4 codewords: 4 independent serial-d chains (ILP=4) ----
        #pragma unroll 1
        for (int kb = 0; kb < Kc; kb += 4) {
            const unsigned r0 = scb_addr + (unsigned)kb * (Dc * 4);
            ull a0 = 0ull, a1 = 0ull, a2 = 0ull, a3 = 0ull;

            #pragma unroll
            for (int g = 0; g < 16; g++) {
                float f00, f01, f02, f03, f10, f11, f12, f13;
                float f20, f21, f22, f23, f30, f31, f32, f33;
                asm("ld.shared.v4.f32 {%0,%1,%2,%3}, [%4];"
                    : "=f"(f00), "=f"(f01), "=f"(f02), "=f"(f03)
                    : "r"(r0 + g * 16));
                asm("ld.shared.v4.f32 {%0,%1,%2,%3}, [%4];"
                    : "=f"(f10), "=f"(f11), "=f"(f12), "=f"(f13)
                    : "r"(r0 + 256 + g * 16));
                asm("ld.shared.v4.f32 {%0,%1,%2,%3}, [%4];"
                    : "=f"(f20), "=f"(f21), "=f"(f22), "=f"(f23)
                    : "r"(r0 + 512 + g * 16));
                asm("ld.shared.v4.f32 {%0,%1,%2,%3}, [%4];"
                    : "=f"(f30), "=f"(f31), "=f"(f32), "=f"(f33)
                    : "r"(r0 + 768 + g * 16));
                // d-step 4g: all 4 chains, then 4g+1, ... (max ILP between deps)
                STEP(a0, f00, xv[4 * g + 0]);
                STEP(a1, f10, xv[4 * g + 0]);
                STEP(a2, f20, xv[4 * g + 0]);
                STEP(a3, f30, xv[4 * g + 0]);
                STEP(a0, f01, xv[4 * g + 1]);
                STEP(a1, f11, xv[4 * g + 1]);
                STEP(a2, f21, xv[4 * g + 1]);
                STEP(a3, f31, xv[4 * g + 1]);
                STEP(a0, f02, xv[4 * g + 2]);
                STEP(a1, f12, xv[4 * g + 2]);
                STEP(a2, f22, xv[4 * g + 2]);
                STEP(a3, f32, xv[4 * g + 2]);
                STEP(a0, f03, xv[4 * g + 3]);
                STEP(a1, f13, xv[4 * g + 3]);
                STEP(a2, f23, xv[4 * g + 3]);
                STEP(a3, f33, xv[4 * g + 3]);
            }

            // s1 = round(-2*dot + xn); score = round(s1 + cn); ascending k, strict <
            ull sp[4];
            asm("fma.rn.f32x2 %0, %1, %2, %3;" : "=l"(sp[0]) : "l"(a0), "l"(m2), "l"(xnp));
            asm("fma.rn.f32x2 %0, %1, %2, %3;" : "=l"(sp[1]) : "l"(a1), "l"(m2), "l"(xnp));
            asm("fma.rn.f32x2 %0, %1, %2, %3;" : "=l"(sp[2]) : "l"(a2), "l"(m2), "l"(xnp));
            asm("fma.rn.f32x2 %0, %1, %2, %3;" : "=l"(sp[3]) : "l"(a3), "l"(m2), "l"(xnp));
            #pragma unroll
            for (int q = 0; q < 4; q++) {
                float p0, p1;
                asm("mov.b64 {%0, %1}, %2;" : "=f"(p0), "=f"(p1) : "l"(sp[q]));
                const float cn = scn[kb + q];
                float sc;
                sc = __fadd_rn(p0, cn); if (sc < best0) { best0 = sc; bi0 = kb + q; }
                sc = __fadd_rn(p1, cn); if (sc < best1) { best1 = sc; bi1 = kb + q; }
            }
        }

        // ---- gather + write both tokens, both outputs ----
        float* o0 = out + (size_t)b * DT + t0;
        float* o1 = o0 + THREADS;
        const float4* q0 = (const float4*)(scb + bi0 * Dc);
        const float4* q1 = (const float4*)(scb + bi1 * Dc);
        #pragma unroll
        for (int g = 0; g < 16; g++) {
            const float4 qa = q0[g];
            const float4 qb = q1[g];
            const size_t r = (size_t)(4 * g) * Tc;
            o0[r] = qa.x; o0[r + Tc] = qa.y; o0[r + 2 * Tc] = qa.z; o0[r + 3 * Tc] = qa.w;
            o1[r] = qb.x; o1[r + Tc] = qb.y; o1[r + 2 * Tc] = qb.z; o1[r + 3 * Tc] = qb.w;
            if (write_second) {
                float* p0 = o0 + (size_t)Bc * DT;
                float* p1 = o1 + (size_t)Bc * DT;
                p0[r] = qa.x; p0[r + Tc] = qa.y; p0[r + 2 * Tc] = qa.z; p0[r + 3 * Tc] = qa.w;
                p1[r] = qb.x; p1[r + Tc] = qb.y; p1[r + 2 * Tc] = qb.z; p1[r + 3 * Tc] = qb.w;
            }
        }
    }
}

extern "C" void kernel_launch(void* const* d_in, const int* in_sizes, int n_in,
                              void* d_out, int out_size)
{
    const float* x  = (const float*)d_in[0];   // [16, 64, 8192] fp32
    const float* cb = (const float*)d_in[1];   // [512, 64] fp32
    float* out = (float*)d_out;                // 2 x [16,64,8192]

    static int smem_set = 0;
    if (!smem_set) {
        cudaFuncSetAttribute(vq_kernel,
                             cudaFuncAttributeMaxDynamicSharedMemorySize,
                             SMEM_BYTES);
        smem_set = 1;
    }

    const int write_second = (out_size >= 2 * Bc * DT) ? 1 : 0;
    vq_kernel<<<GRID, THREADS, SMEM_BYTES>>>(x, cb, out, write_second);
}